// round 2
// baseline (speedup 1.0000x reference)
#include <cuda_runtime.h>

#define NN 100000
#define NR 8
#define HD 16
#define NE 3200000

// Scratch (device globals — no allocations allowed)
__device__ float d_Y[(size_t)NN * NR * HD];   // 51.2 MB: Y[node][r][k] = x[node] @ W[r]
__device__ float d_agg[(size_t)NN * HD];      // 6.4 MB accumulator
__device__ float d_h[(size_t)NN * HD];        // 6.4 MB layer-1 output
__device__ int   d_cnt[(size_t)NN * NR];      // 3.2 MB per-(dst,rel) edge counts

__device__ __forceinline__ void fma4(float4& y, float a, const float4 w) {
    y.x = fmaf(a, w.x, y.x);
    y.y = fmaf(a, w.y, y.y);
    y.z = fmaf(a, w.z, y.z);
    y.w = fmaf(a, w.w, y.w);
}

// y(1x16) = x(1x16) @ W(16x16), W in shared as float4 rows
__device__ __forceinline__ void mat16(const float* xr, const float4* Ws,
                                      float4& y0, float4& y1, float4& y2, float4& y3) {
#pragma unroll
    for (int j = 0; j < HD; j++) {
        float xj = xr[j];
        fma4(y0, xj, Ws[j * 4 + 0]);
        fma4(y1, xj, Ws[j * 4 + 1]);
        fma4(y2, xj, Ws[j * 4 + 2]);
        fma4(y3, xj, Ws[j * 4 + 3]);
    }
}

__device__ __forceinline__ void load16(const float* __restrict__ p, float* xr) {
    const float4* p4 = (const float4*)p;
    float4 t;
    t = p4[0]; xr[0]  = t.x; xr[1]  = t.y; xr[2]  = t.z; xr[3]  = t.w;
    t = p4[1]; xr[4]  = t.x; xr[5]  = t.y; xr[6]  = t.z; xr[7]  = t.w;
    t = p4[2]; xr[8]  = t.x; xr[9]  = t.y; xr[10] = t.z; xr[11] = t.w;
    t = p4[3]; xr[12] = t.x; xr[13] = t.y; xr[14] = t.z; xr[15] = t.w;
}

__global__ void zero_kernel() {
    int i = blockIdx.x * blockDim.x + threadIdx.x;
    if (i < NN * HD) d_agg[i] = 0.0f;
    if (i < NN * NR) d_cnt[i] = 0;
}

__global__ void count_kernel(const int* __restrict__ dst, const int* __restrict__ et) {
    int e = blockIdx.x * blockDim.x + threadIdx.x;
    if (e < NE) atomicAdd(&d_cnt[dst[e] * NR + et[e]], 1);
}

// Y[node][r][:] = x[node] @ W[r].  grid.y = relation (all threads in block share r ->
// broadcast LDS, zero bank conflicts).
template <int LAYER>
__global__ void y_kernel(const float* __restrict__ xext, const float* __restrict__ W) {
    __shared__ float4 Ws[HD * 4];  // 16x16 floats = 1 KB
    int r = blockIdx.y;
    const float4* Wr = (const float4*)(W + (size_t)r * HD * HD);
    for (int i = threadIdx.x; i < HD * 4; i += blockDim.x) Ws[i] = Wr[i];
    __syncthreads();

    int node = blockIdx.x * blockDim.x + threadIdx.x;
    if (node >= NN) return;

    const float* x = (LAYER == 1) ? xext : d_h;
    float xr[HD];
    load16(x + (size_t)node * HD, xr);

    float4 y0 = make_float4(0.f, 0.f, 0.f, 0.f), y1 = y0, y2 = y0, y3 = y0;
    mat16(xr, Ws, y0, y1, y2, y3);

    float4* yp = (float4*)(d_Y + ((size_t)node * NR + r) * HD);
    yp[0] = y0; yp[1] = y1; yp[2] = y2; yp[3] = y3;
}

// One thread per edge: agg[dst] += Y[src][et] / cnt[dst][et]
__global__ void edge_kernel(const int* __restrict__ src, const int* __restrict__ dst,
                            const int* __restrict__ et) {
    int e = blockIdx.x * blockDim.x + threadIdx.x;
    if (e >= NE) return;
    int s = src[e], d = dst[e], t = et[e];
    int c = d_cnt[d * NR + t];
    float norm = 1.0f / (float)(c > 0 ? c : 1);

    const float4* yp = (const float4*)(d_Y + ((size_t)s * NR + t) * HD);
    float4 m0 = yp[0], m1 = yp[1], m2 = yp[2], m3 = yp[3];

    float* o = d_agg + (size_t)d * HD;
    asm volatile("red.global.add.v4.f32 [%0], {%1,%2,%3,%4};"
                 :: "l"(o + 0), "f"(m0.x * norm), "f"(m0.y * norm), "f"(m0.z * norm), "f"(m0.w * norm)
                 : "memory");
    asm volatile("red.global.add.v4.f32 [%0], {%1,%2,%3,%4};"
                 :: "l"(o + 4), "f"(m1.x * norm), "f"(m1.y * norm), "f"(m1.z * norm), "f"(m1.w * norm)
                 : "memory");
    asm volatile("red.global.add.v4.f32 [%0], {%1,%2,%3,%4};"
                 :: "l"(o + 8), "f"(m2.x * norm), "f"(m2.y * norm), "f"(m2.z * norm), "f"(m2.w * norm)
                 : "memory");
    asm volatile("red.global.add.v4.f32 [%0], {%1,%2,%3,%4};"
                 :: "l"(o + 12), "f"(m3.x * norm), "f"(m3.y * norm), "f"(m3.z * norm), "f"(m3.w * norm)
                 : "memory");
}

// h = relu(agg + x @ root1 + b1); also reset agg for layer 2.
__global__ void fin1_kernel(const float* __restrict__ x, const float* __restrict__ root,
                            const float* __restrict__ bias) {
    __shared__ float4 Rs[HD * 4];
    __shared__ float bs[HD];
    for (int i = threadIdx.x; i < HD * 4; i += blockDim.x) Rs[i] = ((const float4*)root)[i];
    if (threadIdx.x < HD) bs[threadIdx.x] = bias[threadIdx.x];
    __syncthreads();

    int node = blockIdx.x * blockDim.x + threadIdx.x;
    if (node >= NN) return;

    float xr[HD];
    load16(x + (size_t)node * HD, xr);

    float4 y0 = make_float4(bs[0], bs[1], bs[2], bs[3]);
    float4 y1 = make_float4(bs[4], bs[5], bs[6], bs[7]);
    float4 y2 = make_float4(bs[8], bs[9], bs[10], bs[11]);
    float4 y3 = make_float4(bs[12], bs[13], bs[14], bs[15]);
    mat16(xr, Rs, y0, y1, y2, y3);

    float4* ap = (float4*)(d_agg + (size_t)node * HD);
    float4 a0 = ap[0], a1 = ap[1], a2 = ap[2], a3 = ap[3];
    y0.x = fmaxf(y0.x + a0.x, 0.f); y0.y = fmaxf(y0.y + a0.y, 0.f);
    y0.z = fmaxf(y0.z + a0.z, 0.f); y0.w = fmaxf(y0.w + a0.w, 0.f);
    y1.x = fmaxf(y1.x + a1.x, 0.f); y1.y = fmaxf(y1.y + a1.y, 0.f);
    y1.z = fmaxf(y1.z + a1.z, 0.f); y1.w = fmaxf(y1.w + a1.w, 0.f);
    y2.x = fmaxf(y2.x + a2.x, 0.f); y2.y = fmaxf(y2.y + a2.y, 0.f);
    y2.z = fmaxf(y2.z + a2.z, 0.f); y2.w = fmaxf(y2.w + a2.w, 0.f);
    y3.x = fmaxf(y3.x + a3.x, 0.f); y3.y = fmaxf(y3.y + a3.y, 0.f);
    y3.z = fmaxf(y3.z + a3.z, 0.f); y3.w = fmaxf(y3.w + a3.w, 0.f);

    float4* hp = (float4*)(d_h + (size_t)node * HD);
    hp[0] = y0; hp[1] = y1; hp[2] = y2; hp[3] = y3;

    // reset agg for layer 2 (this thread exclusively owns node's slice)
    float4 z = make_float4(0.f, 0.f, 0.f, 0.f);
    ap[0] = z; ap[1] = z; ap[2] = z; ap[3] = z;
}

// out = log_softmax(agg + h @ root2 + b2)
__global__ void fin2_kernel(const float* __restrict__ root, const float* __restrict__ bias,
                            float* __restrict__ out) {
    __shared__ float4 Rs[HD * 4];
    __shared__ float bs[HD];
    for (int i = threadIdx.x; i < HD * 4; i += blockDim.x) Rs[i] = ((const float4*)root)[i];
    if (threadIdx.x < HD) bs[threadIdx.x] = bias[threadIdx.x];
    __syncthreads();

    int node = blockIdx.x * blockDim.x + threadIdx.x;
    if (node >= NN) return;

    float xr[HD];
    load16(d_h + (size_t)node * HD, xr);

    float4 y0 = make_float4(bs[0], bs[1], bs[2], bs[3]);
    float4 y1 = make_float4(bs[4], bs[5], bs[6], bs[7]);
    float4 y2 = make_float4(bs[8], bs[9], bs[10], bs[11]);
    float4 y3 = make_float4(bs[12], bs[13], bs[14], bs[15]);
    mat16(xr, Rs, y0, y1, y2, y3);

    const float4* ap = (const float4*)(d_agg + (size_t)node * HD);
    float4 a0 = ap[0], a1 = ap[1], a2 = ap[2], a3 = ap[3];

    float o[HD];
    o[0]  = y0.x + a0.x; o[1]  = y0.y + a0.y; o[2]  = y0.z + a0.z; o[3]  = y0.w + a0.w;
    o[4]  = y1.x + a1.x; o[5]  = y1.y + a1.y; o[6]  = y1.z + a1.z; o[7]  = y1.w + a1.w;
    o[8]  = y2.x + a2.x; o[9]  = y2.y + a2.y; o[10] = y2.z + a2.z; o[11] = y2.w + a2.w;
    o[12] = y3.x + a3.x; o[13] = y3.y + a3.y; o[14] = y3.z + a3.z; o[15] = y3.w + a3.w;

    float m = o[0];
#pragma unroll
    for (int k = 1; k < HD; k++) m = fmaxf(m, o[k]);
    float s = 0.f;
#pragma unroll
    for (int k = 0; k < HD; k++) s += expf(o[k] - m);
    float l = m + logf(s);

    float4* op = (float4*)(out + (size_t)node * HD);
    op[0] = make_float4(o[0] - l, o[1] - l, o[2] - l, o[3] - l);
    op[1] = make_float4(o[4] - l, o[5] - l, o[6] - l, o[7] - l);
    op[2] = make_float4(o[8] - l, o[9] - l, o[10] - l, o[11] - l);
    op[3] = make_float4(o[12] - l, o[13] - l, o[14] - l, o[15] - l);
}

extern "C" void kernel_launch(void* const* d_in, const int* in_sizes, int n_in,
                              void* d_out, int out_size) {
    const float* embed = (const float*)d_in[0];
    const float* W1    = (const float*)d_in[1];
    const float* root1 = (const float*)d_in[2];
    const float* b1    = (const float*)d_in[3];
    const float* W2    = (const float*)d_in[4];
    const float* root2 = (const float*)d_in[5];
    const float* b2    = (const float*)d_in[6];
    const int*   eidx  = (const int*)d_in[7];   // [2, NE]
    const int*   etyp  = (const int*)d_in[8];   // [NE]
    float* out = (float*)d_out;

    const int* src = eidx;
    const int* dst = eidx + NE;

    const int TB = 256;
    int node_blocks = (NN + TB - 1) / TB;
    int zero_blocks = (NN * HD + TB - 1) / TB;
    int edge_blocks = (NE + TB - 1) / TB;

    zero_kernel<<<zero_blocks, TB>>>();
    count_kernel<<<edge_blocks, TB>>>(dst, etyp);

    // Layer 1
    y_kernel<1><<<dim3(node_blocks, NR), TB>>>(embed, W1);
    edge_kernel<<<edge_blocks, TB>>>(src, dst, etyp);
    fin1_kernel<<<node_blocks, TB>>>(embed, root1, b1);

    // Layer 2
    y_kernel<2><<<dim3(node_blocks, NR), TB>>>(nullptr, W2);
    edge_kernel<<<edge_blocks, TB>>>(src, dst, etyp);
    fin2_kernel<<<node_blocks, TB>>>(root2, b2, out);
}

// round 3
// speedup vs baseline: 1.1883x; 1.1883x over previous
#include <cuda_runtime.h>

#define NN 100000
#define NR 8
#define HD 16
#define NE 3200000
#define NSEG (NN * NR)          // 800000
#define SCAN_NB ((NSEG + 1023) / 1024)   // 782

// Device scratch (no allocations allowed)
__device__ int   d_cnt[NSEG];
__device__ int   d_off[NSEG + 1];
__device__ int   d_cur[NSEG];
__device__ int   d_bsum[1024];
__device__ int   d_sorted[NE];        // src ids sorted by (dst, rel)
__device__ float d_h[(size_t)NN * HD];

// ---------------------------------------------------------------- sort phase
__global__ void zero_kernel() {
    int i = blockIdx.x * blockDim.x + threadIdx.x;
    if (i < NSEG) d_cnt[i] = 0;
}

__global__ void count_kernel(const int* __restrict__ dst, const int* __restrict__ et) {
    int e = blockIdx.x * blockDim.x + threadIdx.x;
    if (e < NE) atomicAdd(&d_cnt[dst[e] * NR + et[e]], 1);
}

// Per-block (1024 elems) exclusive scan; block totals to d_bsum.
__global__ void scan1_kernel() {
    __shared__ int wsum[8];
    int t = threadIdx.x;
    int base = blockIdx.x * 1024 + t * 4;
    int v0 = (base + 0 < NSEG) ? d_cnt[base + 0] : 0;
    int v1 = (base + 1 < NSEG) ? d_cnt[base + 1] : 0;
    int v2 = (base + 2 < NSEG) ? d_cnt[base + 2] : 0;
    int v3 = (base + 3 < NSEG) ? d_cnt[base + 3] : 0;
    int tot = v0 + v1 + v2 + v3;

    int lane = t & 31, wid = t >> 5;
    int sc = tot;
#pragma unroll
    for (int o = 1; o < 32; o <<= 1) {
        int n = __shfl_up_sync(0xffffffff, sc, o);
        if (lane >= o) sc += n;
    }
    if (lane == 31) wsum[wid] = sc;
    __syncthreads();
    if (t < 8) {
        int w = wsum[t];
#pragma unroll
        for (int o = 1; o < 8; o <<= 1) {
            int n = __shfl_up_sync(0xff, w, o);
            if (t >= o) w += n;
        }
        wsum[t] = w;  // inclusive over warps
    }
    __syncthreads();
    int woff = (wid == 0) ? 0 : wsum[wid - 1];
    int p = woff + sc - tot;  // exclusive prefix of this thread's chunk
    if (base + 0 < NSEG) d_off[base + 0] = p;  p += v0;
    if (base + 1 < NSEG) d_off[base + 1] = p;  p += v1;
    if (base + 2 < NSEG) d_off[base + 2] = p;  p += v2;
    if (base + 3 < NSEG) d_off[base + 3] = p;
    if (t == 0) d_bsum[blockIdx.x] = wsum[7];
}

// Single-block exclusive scan of block sums (<=1024).
__global__ void scan2_kernel(int nb) {
    __shared__ int s[1024];
    int t = threadIdx.x;
    s[t] = (t < nb) ? d_bsum[t] : 0;
    __syncthreads();
    for (int o = 1; o < 1024; o <<= 1) {
        int v = (t >= o) ? s[t - o] : 0;
        __syncthreads();
        s[t] += v;
        __syncthreads();
    }
    d_bsum[t] = (t == 0) ? 0 : s[t - 1];
}

__global__ void scan3_kernel() {
    int i = blockIdx.x * blockDim.x + threadIdx.x;
    if (i < NSEG) {
        int o = d_off[i] + d_bsum[i >> 10];
        d_off[i] = o;
        d_cur[i] = o;
    }
    if (i == 0) d_off[NSEG] = NE;
}

__global__ void scatter_kernel(const int* __restrict__ src, const int* __restrict__ dst,
                               const int* __restrict__ et) {
    int e = blockIdx.x * blockDim.x + threadIdx.x;
    if (e >= NE) return;
    int seg = dst[e] * NR + et[e];
    int pos = atomicAdd(&d_cur[seg], 1);
    d_sorted[pos] = src[e];
}

// ---------------------------------------------------------------- fused layer
// One block = 32 nodes x 8 relations (256 threads).
// Phase 1: thread (nd, r) accumulates mean of x[src] over its sorted segment.
// Phase 2: thread (nd, j) computes output comps 2j, 2j+1 = bias + x_d@root + sum_r S_r@W_r.
template <bool FIRST>
__global__ void __launch_bounds__(256)
layer_kernel(const float* __restrict__ x, const float* __restrict__ W,
             const float* __restrict__ root, const float* __restrict__ bias,
             float* __restrict__ out) {
    __shared__ float Wsm[NR * HD * HD];      // 8 KB
    __shared__ float Rsm[HD * HD];           // 1 KB
    __shared__ float Bsm[HD];
    __shared__ float Ssm[32][NR * HD + 4];   // pad 132 -> conflict-free across nd
    __shared__ float Xd[32][HD + 1];         // pad 17

    int t = threadIdx.x;
    for (int i = t; i < NR * HD * HD; i += 256) Wsm[i] = W[i];
    for (int i = t; i < HD * HD; i += 256) Rsm[i] = root[i];
    if (t < HD) Bsm[t] = bias[t];

    int nd = t >> 3;                 // 0..31
    int j  = t & 7;                  // 0..7
    int node = blockIdx.x * 32 + nd; // NN = 32*3125 exactly, no guard needed

    // Cooperative load of x[dst] rows for the root term
    {
        const float2* xp = (const float2*)(x + (size_t)node * HD);
        float2 v = xp[j];
        Xd[nd][j * 2] = v.x;
        Xd[nd][j * 2 + 1] = v.y;
    }

    // Phase 1: segment aggregation (atomic-free)
    {
        int seg = node * NR + j;
        int beg = d_off[seg], end = d_off[seg + 1];
        float4 a0 = make_float4(0.f, 0.f, 0.f, 0.f), a1 = a0, a2 = a0, a3 = a0;
        for (int e = beg; e < end; e++) {
            int s = d_sorted[e];
            const float4* xp = (const float4*)(x + (size_t)s * HD);
            float4 v0 = xp[0], v1 = xp[1], v2 = xp[2], v3 = xp[3];
            a0.x += v0.x; a0.y += v0.y; a0.z += v0.z; a0.w += v0.w;
            a1.x += v1.x; a1.y += v1.y; a1.z += v1.z; a1.w += v1.w;
            a2.x += v2.x; a2.y += v2.y; a2.z += v2.z; a2.w += v2.w;
            a3.x += v3.x; a3.y += v3.y; a3.z += v3.z; a3.w += v3.w;
        }
        float nrm = (end > beg) ? 1.0f / (float)(end - beg) : 0.0f;
        float* sp = &Ssm[nd][j * HD];
        sp[0]  = a0.x * nrm; sp[1]  = a0.y * nrm; sp[2]  = a0.z * nrm; sp[3]  = a0.w * nrm;
        sp[4]  = a1.x * nrm; sp[5]  = a1.y * nrm; sp[6]  = a1.z * nrm; sp[7]  = a1.w * nrm;
        sp[8]  = a2.x * nrm; sp[9]  = a2.y * nrm; sp[10] = a2.z * nrm; sp[11] = a2.w * nrm;
        sp[12] = a3.x * nrm; sp[13] = a3.y * nrm; sp[14] = a3.z * nrm; sp[15] = a3.w * nrm;
    }
    __syncthreads();

    // Phase 2: two output components per thread
    int k0 = j * 2, k1 = k0 + 1;
    float v0 = Bsm[k0], v1 = Bsm[k1];
#pragma unroll
    for (int k = 0; k < HD; k++) {
        float xv = Xd[nd][k];
        v0 = fmaf(xv, Rsm[k * HD + k0], v0);
        v1 = fmaf(xv, Rsm[k * HD + k1], v1);
    }
#pragma unroll
    for (int rr = 0; rr < NR; rr++) {
#pragma unroll
        for (int k = 0; k < HD; k++) {
            float sv = Ssm[nd][rr * HD + k];
            v0 = fmaf(sv, Wsm[rr * HD * HD + k * HD + k0], v0);
            v1 = fmaf(sv, Wsm[rr * HD * HD + k * HD + k1], v1);
        }
    }

    if (FIRST) {
        v0 = fmaxf(v0, 0.f);
        v1 = fmaxf(v1, 0.f);
        float2* op = (float2*)(out + (size_t)node * HD);
        op[j] = make_float2(v0, v1);
    } else {
        // log_softmax across the 8-thread group (xor 1,2,4 stays within group)
        float m = fmaxf(v0, v1);
#pragma unroll
        for (int o = 1; o < 8; o <<= 1) m = fmaxf(m, __shfl_xor_sync(0xffffffff, m, o));
        float s = expf(v0 - m) + expf(v1 - m);
#pragma unroll
        for (int o = 1; o < 8; o <<= 1) s += __shfl_xor_sync(0xffffffff, s, o);
        float l = m + logf(s);
        float2* op = (float2*)(out + (size_t)node * HD);
        op[j] = make_float2(v0 - l, v1 - l);
    }
}

// ---------------------------------------------------------------- launch
extern "C" void kernel_launch(void* const* d_in, const int* in_sizes, int n_in,
                              void* d_out, int out_size) {
    const float* embed = (const float*)d_in[0];
    const float* W1    = (const float*)d_in[1];
    const float* root1 = (const float*)d_in[2];
    const float* b1    = (const float*)d_in[3];
    const float* W2    = (const float*)d_in[4];
    const float* root2 = (const float*)d_in[5];
    const float* b2    = (const float*)d_in[6];
    const int*   eidx  = (const int*)d_in[7];   // [2, NE]
    const int*   etyp  = (const int*)d_in[8];   // [NE]
    float* out = (float*)d_out;

    const int* src = eidx;
    const int* dst = eidx + NE;

    const int TB = 256;
    int seg_blocks  = (NSEG + TB - 1) / TB;
    int edge_blocks = (NE + TB - 1) / TB;
    int node_blocks = NN / 32;  // 3125

    float* hbuf;
    cudaGetSymbolAddress((void**)&hbuf, d_h);

    // Sort edges by (dst, relation) — shared by both layers
    zero_kernel<<<seg_blocks, TB>>>();
    count_kernel<<<edge_blocks, TB>>>(dst, etyp);
    scan1_kernel<<<SCAN_NB, 256>>>();
    scan2_kernel<<<1, 1024>>>(SCAN_NB);
    scan3_kernel<<<seg_blocks, TB>>>();
    scatter_kernel<<<edge_blocks, TB>>>(src, dst, etyp);

    // Fully fused layers
    layer_kernel<true><<<node_blocks, TB>>>(embed, W1, root1, b1, hbuf);
    layer_kernel<false><<<node_blocks, TB>>>(hbuf, W2, root2, b2, out);
}